// round 3
// baseline (speedup 1.0000x reference)
#include <cuda_runtime.h>
#include <math.h>

// Preisach hysteresis:
//   state row j = prefix of +1 of length c_j, then -1 (within lower triangle).
//   up-step h:   rows with x[j] < h  -> c_j = j+1
//   down-step h: all rows            -> c_j = min(c_j, K), K = #{k: x[k] <= h}
//   b[t] = (sum_j (2*P_j(c_j) - RowTot_j)) / 32896 * scale + offset
// Chunked over time (80 chunks x 25 steps) via function composition
// (f(c)=min(c,m) or f(c)=v is closed under composition).

#define NN 256
#define TT 2000
#define LSIZE 33152          // sum_j (j+2)
#define CHUNK 25
#define NCHUNK 80
#define QSCALE 8192.0f

__device__ int g_Li[LSIZE];        // quantized row-local prefix sums of softplus(density)
__device__ int g_RowTotI[NN];
__device__ int g_meta[TT];         // -1 up, -2 flat, else K (down)
__device__ int g_fv[NCHUNK * NN];  // per-(chunk,row) transfer function
__device__ int g_centry[NCHUNK * NN];
__device__ int g_TotalI;

__device__ __forceinline__ float xval(int i) {
    // replicate jnp.linspace(0,1,256) in f32: i * fl(1/255), endpoint exact
    return (i == NN - 1) ? 1.0f : (float)i * (1.0f / 255.0f);
}
__device__ __forceinline__ float softplusf(float v) {
    return fmaxf(v, 0.0f) + log1pf(expf(-fabsf(v)));
}

// K1: per-row prefix sums of softplus(raw), quantized. One warp per row.
__global__ void k1_prefix(const float* __restrict__ raw) {
    int warp = (blockIdx.x * blockDim.x + threadIdx.x) >> 5;
    int lane = threadIdx.x & 31;
    if (warp >= NN) return;
    int j  = warp;
    int sj = j * (j + 1) / 2;
    int oj = sj + j;
    int n  = j + 1;
    if (lane == 0) g_Li[oj] = 0;
    float carry = 0.0f;
    for (int base = 0; base < n; base += 32) {
        int idx = base + lane;
        float v = (idx < n) ? softplusf(raw[sj + idx]) : 0.0f;
        #pragma unroll
        for (int d = 1; d < 32; d <<= 1) {
            float t = __shfl_up_sync(0xffffffffu, v, d);
            if (lane >= d) v += t;
        }
        float pref = carry + v;
        if (idx < n) {
            int q = __float2int_rn(pref * QSCALE);
            g_Li[oj + 1 + idx] = q;
            if (idx == n - 1) g_RowTotI[j] = q;
        }
        carry += __shfl_sync(0xffffffffu, v, 31);
    }
}

// K2: per-step direction / down-level K
__global__ void k2_meta(const float* __restrict__ h) {
    int t = blockIdx.x * blockDim.x + threadIdx.x;
    if (t >= TT) return;
    float hp = (t == 0) ? 0.0f : h[t - 1];
    float hc = h[t];
    int m;
    if (hc > hp) {
        m = -1;
    } else if (hc < hp) {
        int K = 0;
        #pragma unroll 8
        for (int k = 0; k < NN; k++) K += (xval(k) <= hc) ? 1 : 0;
        m = K;
    } else {
        m = -2;
    }
    g_meta[t] = m;
}

// K3: compose per-(chunk,row) transfer function
__global__ void k3_compose(const float* __restrict__ h) {
    __shared__ int   sm[CHUNK];
    __shared__ float shh[CHUNK];
    int ci = blockIdx.x;
    int j  = threadIdx.x;
    int t0 = ci * CHUNK;
    if (j < CHUNK) { sm[j] = g_meta[t0 + j]; shh[j] = h[t0 + j]; }
    __syncthreads();
    float xj = xval(j);
    bool isC = false;
    int v = 0, m = 511;
    for (int s = 0; s < CHUNK; s++) {
        int mt = sm[s];
        if (mt == -1) {
            if (xj < shh[s]) { isC = true; v = j + 1; }
        } else if (mt >= 0) {
            if (isC) v = min(v, mt); else m = min(m, mt);
        }
    }
    g_fv[ci * NN + j] = isC ? (512 + v) : m;
}

// K4: sequential scan over chunk functions -> entry state per chunk; Total reduce
__global__ void k4_scan() {
    int j = threadIdx.x;
    int c = 0;
    for (int i = 0; i < NCHUNK; i++) {
        g_centry[i * NN + j] = c;
        int f = g_fv[i * NN + j];
        c = (f >= 512) ? (f - 512) : min(c, f);
    }
    __shared__ int red[NN];
    red[j] = g_RowTotI[j];
    __syncthreads();
    for (int off = 128; off > 0; off >>= 1) {
        if (j < off) red[j] += red[j + off];
        __syncthreads();
    }
    if (j == 0) g_TotalI = red[0];
}

// K5: replay each chunk, emit outputs. 32 threads/CTA, 8 rows/lane, REDUX sum.
__global__ void k5_main(const float* __restrict__ h,
                        const float* __restrict__ offset,
                        const float* __restrict__ scale,
                        float* __restrict__ out) {
    __shared__ int   sm[CHUNK];
    __shared__ float shh[CHUNK];
    int ci   = blockIdx.x;
    int lane = threadIdx.x;
    int t0   = ci * CHUNK;
    if (lane < CHUNK) { sm[lane] = g_meta[t0 + lane]; shh[lane] = h[t0 + lane]; }
    __syncwarp();

    int   c[8], rvi[8], rvfull[8], oj[8];
    float xq[8];
    #pragma unroll
    for (int q = 0; q < 8; q++) {
        int j = lane + 32 * q;
        oj[q] = j * (j + 3) / 2;
        xq[q] = xval(j);
        c[q]  = g_centry[ci * NN + j];
        rvi[q]    = 2 * g_Li[oj[q] + c[q]];
        rvfull[q] = 2 * g_RowTotI[j];
    }
    float scl = scale[0], off = offset[0];
    int totalI = g_TotalI;
    const float invq   = 1.0f / QSCALE;
    const float invtri = 1.0f / 32896.0f;

    for (int s = 0; s < CHUNK; s++) {
        int mt = sm[s];
        if (mt == -1) {
            float hc = shh[s];
            #pragma unroll
            for (int q = 0; q < 8; q++) {
                int j = lane + 32 * q;
                if (xq[q] < hc) { c[q] = j + 1; rvi[q] = rvfull[q]; }
            }
        } else if (mt >= 0) {
            #pragma unroll
            for (int q = 0; q < 8; q++) {
                if (mt < c[q]) { c[q] = mt; rvi[q] = 2 * g_Li[oj[q] + mt]; }
            }
        }
        int s8 = ((rvi[0] + rvi[1]) + (rvi[2] + rvi[3])) +
                 ((rvi[4] + rvi[5]) + (rvi[6] + rvi[7]));
        int tot = __reduce_add_sync(0xffffffffu, s8);
        if (lane == 0) {
            float numer = (float)(tot - totalI) * invq;
            out[t0 + s] = numer * invtri * scl + off;
        }
    }
}

extern "C" void kernel_launch(void* const* d_in, const int* in_sizes, int n_in,
                              void* d_out, int out_size) {
    const float* h      = (const float*)d_in[0];
    const float* raw    = (const float*)d_in[1];
    const float* offset = (const float*)d_in[2];
    const float* scale  = (const float*)d_in[3];
    float* out = (float*)d_out;

    k1_prefix<<<16, 512>>>(raw);
    k2_meta<<<8, 256>>>(h);
    k3_compose<<<NCHUNK, 256>>>(h);
    k4_scan<<<1, 256>>>();
    k5_main<<<NCHUNK, 32>>>(h, offset, scale, out);
}

// round 5
// speedup vs baseline: 1.6237x; 1.6237x over previous
#include <cuda_runtime.h>
#include <math.h>

// Preisach hysteresis:
//   state row j = prefix of +1 of length c_j, then -1 (within lower triangle).
//   up-step h:   rows with x[j] < h  -> c_j = j+1
//   down-step h: all rows            -> c_j = min(c_j, K), K = #{k: x[k] <= h}
//   b[t] = (sum_j (2*P_j(c_j) - RowTot_j)) / 32896 * scale + offset
// Chunked over time (80 chunks x 25 steps) via function composition.
// R3: k4 scan made latency-parallel (transposed g_fvT, 20x int4 prefetch,
//     full-unroll register scan); k2 fused into k3.

#define NN 256
#define TT 2000
#define LSIZE 33152          // sum_j (j+2)
#define CHUNK 25
#define NCHUNK 80
#define QSCALE 8192.0f

__device__ int g_Li[LSIZE];        // quantized row-local prefix sums of softplus(density)
__device__ int g_RowTotI[NN];
__device__ int g_meta[TT];         // -1 up, -2 flat, else K (down)
__device__ __align__(16) int g_fvT[NN * NCHUNK];   // [row][chunk] transfer functions
__device__ int g_centry[NCHUNK * NN];              // [chunk][row] entry states
__device__ int g_TotalI;

__device__ __forceinline__ float xval(int i) {
    // replicate jnp.linspace(0,1,256) in f32: i * fl(1/255), endpoint exact
    return (i == NN - 1) ? 1.0f : (float)i * (1.0f / 255.0f);
}
__device__ __forceinline__ float softplusf(float v) {
    return fmaxf(v, 0.0f) + log1pf(expf(-fabsf(v)));
}

// K1: per-row prefix sums of softplus(raw), quantized. One warp per row.
__global__ void k1_prefix(const float* __restrict__ raw) {
    int warp = (blockIdx.x * blockDim.x + threadIdx.x) >> 5;
    int lane = threadIdx.x & 31;
    if (warp >= NN) return;
    int j  = warp;
    int sj = j * (j + 1) / 2;
    int oj = sj + j;
    int n  = j + 1;
    if (lane == 0) g_Li[oj] = 0;
    float carry = 0.0f;
    for (int base = 0; base < n; base += 32) {
        int idx = base + lane;
        float v = (idx < n) ? softplusf(raw[sj + idx]) : 0.0f;
        #pragma unroll
        for (int d = 1; d < 32; d <<= 1) {
            float t = __shfl_up_sync(0xffffffffu, v, d);
            if (lane >= d) v += t;
        }
        float pref = carry + v;
        if (idx < n) {
            int q = __float2int_rn(pref * QSCALE);
            g_Li[oj + 1 + idx] = q;
            if (idx == n - 1) g_RowTotI[j] = q;
        }
        carry += __shfl_sync(0xffffffffu, v, 31);
    }
}

// K3: compute per-step meta for this chunk (fused former k2) and compose
// per-(chunk,row) transfer functions. One CTA per chunk, 256 threads.
__global__ void k3_compose(const float* __restrict__ h) {
    __shared__ int   sm[CHUNK];
    __shared__ float shh[CHUNK];
    int ci = blockIdx.x;
    int j  = threadIdx.x;
    int t0 = ci * CHUNK;

    if (j < CHUNK) {
        int t = t0 + j;
        float hp = (t == 0) ? 0.0f : h[t - 1];
        float hc = h[t];
        int m;
        if (hc > hp) {
            m = -1;
        } else if (hc < hp) {
            int K = 0;
            #pragma unroll 8
            for (int k = 0; k < NN; k++) K += (xval(k) <= hc) ? 1 : 0;
            m = K;
        } else {
            m = -2;
        }
        sm[j] = m; shh[j] = hc;
        g_meta[t] = m;           // consumed by k5
    }
    __syncthreads();

    float xj = xval(j);
    bool isC = false;
    int v = 0, m = 511;
    #pragma unroll
    for (int s = 0; s < CHUNK; s++) {
        int mt = sm[s];
        if (mt == -1) {
            if (xj < shh[s]) { isC = true; v = j + 1; }
        } else if (mt >= 0) {
            if (isC) v = min(v, mt); else m = min(m, mt);
        }
    }
    g_fvT[j * NCHUNK + ci] = isC ? (512 + v) : m;
}

// K4: per-row scan over chunk functions -> entry state per chunk; Total reduce.
// All 80 values prefetched as 20 int4 (MLP~20), scan fully unrolled in regs.
__global__ void k4_scan() {
    int j = threadIdx.x;
    const int4* fv = reinterpret_cast<const int4*>(&g_fvT[j * NCHUNK]);
    int f[NCHUNK];
    #pragma unroll
    for (int b = 0; b < NCHUNK / 4; b++) {
        int4 t = fv[b];
        f[4 * b + 0] = t.x; f[4 * b + 1] = t.y;
        f[4 * b + 2] = t.z; f[4 * b + 3] = t.w;
    }
    int c = 0;
    #pragma unroll
    for (int i = 0; i < NCHUNK; i++) {
        g_centry[i * NN + j] = c;          // coalesced across threads
        int fs = f[i];
        c = (fs >= 512) ? (fs - 512) : min(c, fs);
    }
    __shared__ int red[NN];
    red[j] = g_RowTotI[j];
    __syncthreads();
    for (int off = 128; off > 0; off >>= 1) {
        if (j < off) red[j] += red[j + off];
        __syncthreads();
    }
    if (j == 0) g_TotalI = red[0];
}

// K5: replay each chunk, emit outputs. 32 threads/CTA, 8 rows/lane, REDUX sum.
__global__ void k5_main(const float* __restrict__ h,
                        const float* __restrict__ offset,
                        const float* __restrict__ scale,
                        float* __restrict__ out) {
    __shared__ int   sm[CHUNK];
    __shared__ float shh[CHUNK];
    int ci   = blockIdx.x;
    int lane = threadIdx.x;
    int t0   = ci * CHUNK;
    if (lane < CHUNK) { sm[lane] = g_meta[t0 + lane]; shh[lane] = h[t0 + lane]; }
    __syncwarp();

    int   c[8], rvi[8], rvfull[8], oj[8];
    float xq[8];
    #pragma unroll
    for (int q = 0; q < 8; q++) {
        int j = lane + 32 * q;
        oj[q] = j * (j + 3) / 2;
        xq[q] = xval(j);
        c[q]  = g_centry[ci * NN + j];
        rvi[q]    = 2 * g_Li[oj[q] + c[q]];
        rvfull[q] = 2 * g_RowTotI[j];
    }
    float scl = scale[0], off = offset[0];
    int totalI = g_TotalI;
    const float invq   = 1.0f / QSCALE;
    const float invtri = 1.0f / 32896.0f;

    for (int s = 0; s < CHUNK; s++) {
        int mt = sm[s];
        if (mt == -1) {
            float hc = shh[s];
            #pragma unroll
            for (int q = 0; q < 8; q++) {
                int j = lane + 32 * q;
                if (xq[q] < hc) { c[q] = j + 1; rvi[q] = rvfull[q]; }
            }
        } else if (mt >= 0) {
            #pragma unroll
            for (int q = 0; q < 8; q++) {
                if (mt < c[q]) { c[q] = mt; rvi[q] = 2 * g_Li[oj[q] + mt]; }
            }
        }
        int s8 = ((rvi[0] + rvi[1]) + (rvi[2] + rvi[3])) +
                 ((rvi[4] + rvi[5]) + (rvi[6] + rvi[7]));
        int tot = __reduce_add_sync(0xffffffffu, s8);
        if (lane == 0) {
            float numer = (float)(tot - totalI) * invq;
            out[t0 + s] = numer * invtri * scl + off;
        }
    }
}

extern "C" void kernel_launch(void* const* d_in, const int* in_sizes, int n_in,
                              void* d_out, int out_size) {
    const float* h      = (const float*)d_in[0];
    const float* raw    = (const float*)d_in[1];
    const float* offset = (const float*)d_in[2];
    const float* scale  = (const float*)d_in[3];
    float* out = (float*)d_out;

    k1_prefix<<<16, 512>>>(raw);
    k3_compose<<<NCHUNK, 256>>>(h);
    k4_scan<<<1, 256>>>();
    k5_main<<<NCHUNK, 32>>>(h, offset, scale, out);
}

// round 6
// speedup vs baseline: 2.5787x; 1.5882x over previous
#include <cuda_runtime.h>
#include <math.h>

// Preisach hysteresis:
//   state row j = prefix of +1 of length c_j, then -1 (within lower triangle).
//   up-step h:   rows with x[j] < h  -> c_j = j+1
//   down-step h: all rows            -> c_j = min(c_j, K), K = #{k: x[k] <= h}
//   b[t] = (sum_j (2*P_j(c_j) - RowTot_j)) / 32896 * scale + offset
// R5: per-step independent expansion — each warp replays its chunk-local
//     prefix in registers (no memory in the loop), then does 8 parallel
//     Li lookups + REDUX. Removes the 25-step serial LDG chain of old k5.

#define NN 256
#define TT 2000
#define LSIZE 33152          // sum_j (j+2)
#define CHUNK 25
#define NCHUNK 80
#define QSCALE 8192.0f

__device__ int g_Li[LSIZE];        // quantized row-local prefix sums of softplus(density)
__device__ int g_RowTotI[NN];
__device__ int g_meta[TT];         // -1 up, -2 flat, else K (down)
__device__ __align__(16) int g_fvT[NN * NCHUNK];   // [row][chunk] transfer functions
__device__ int g_centry[NCHUNK * NN];              // [chunk][row] entry states
__device__ int g_TotalI;

__device__ __forceinline__ float xval(int i) {
    // replicate jnp.linspace(0,1,256) in f32: i * fl(1/255), endpoint exact
    return (i == NN - 1) ? 1.0f : (float)i * (1.0f / 255.0f);
}
__device__ __forceinline__ float softplusf(float v) {
    return fmaxf(v, 0.0f) + log1pf(expf(-fabsf(v)));
}

// KA: fused k1 (row prefix sums, blocks 0..15) + k3 (meta + chunk transfer
// compose, blocks 16..95). 512 threads per block.
__global__ void kA_fused(const float* __restrict__ raw, const float* __restrict__ h) {
    if (blockIdx.x < 16) {
        // ---- k1: per-row prefix sums of softplus(raw), one warp per row ----
        int warp = (blockIdx.x * 512 + threadIdx.x) >> 5;
        int lane = threadIdx.x & 31;
        int j  = warp;
        int sj = j * (j + 1) / 2;
        int oj = sj + j;
        int n  = j + 1;
        if (lane == 0) g_Li[oj] = 0;
        float carry = 0.0f;
        for (int base = 0; base < n; base += 32) {
            int idx = base + lane;
            float v = (idx < n) ? softplusf(raw[sj + idx]) : 0.0f;
            #pragma unroll
            for (int d = 1; d < 32; d <<= 1) {
                float t = __shfl_up_sync(0xffffffffu, v, d);
                if (lane >= d) v += t;
            }
            float pref = carry + v;
            if (idx < n) {
                int q = __float2int_rn(pref * QSCALE);
                g_Li[oj + 1 + idx] = q;
                if (idx == n - 1) g_RowTotI[j] = q;
            }
            carry += __shfl_sync(0xffffffffu, v, 31);
        }
    } else {
        // ---- k3: per-step meta + per-(chunk,row) transfer compose ----
        __shared__ int   sm[CHUNK];
        __shared__ float shh[CHUNK];
        int ci = blockIdx.x - 16;
        int j  = threadIdx.x;
        int t0 = ci * CHUNK;

        if (j < CHUNK) {
            int t = t0 + j;
            float hp = (t == 0) ? 0.0f : h[t - 1];
            float hc = h[t];
            int m;
            if (hc > hp) {
                m = -1;
            } else if (hc < hp) {
                int K = 0;
                #pragma unroll 8
                for (int k = 0; k < NN; k++) K += (xval(k) <= hc) ? 1 : 0;
                m = K;
            } else {
                m = -2;
            }
            sm[j] = m; shh[j] = hc;
            g_meta[t] = m;
        }
        __syncthreads();
        if (j < NN) {
            float xj = xval(j);
            bool isC = false;
            int v = 0, m = 511;
            #pragma unroll
            for (int s = 0; s < CHUNK; s++) {
                int mt = sm[s];
                if (mt == -1) {
                    if (xj < shh[s]) { isC = true; v = j + 1; }
                } else if (mt >= 0) {
                    if (isC) v = min(v, mt); else m = min(m, mt);
                }
            }
            g_fvT[j * NCHUNK + ci] = isC ? (512 + v) : m;
        }
    }
}

// KB: per-row scan over chunk functions -> entry state per chunk; Total reduce.
// All 80 values prefetched as 20 int4 (MLP~20), scan fully unrolled in regs.
__global__ void kB_scan() {
    int j = threadIdx.x;
    const int4* fv = reinterpret_cast<const int4*>(&g_fvT[j * NCHUNK]);
    int f[NCHUNK];
    #pragma unroll
    for (int b = 0; b < NCHUNK / 4; b++) {
        int4 t = fv[b];
        f[4 * b + 0] = t.x; f[4 * b + 1] = t.y;
        f[4 * b + 2] = t.z; f[4 * b + 3] = t.w;
    }
    int c = 0;
    #pragma unroll
    for (int i = 0; i < NCHUNK; i++) {
        g_centry[i * NN + j] = c;          // coalesced across threads
        int fs = f[i];
        c = (fs >= 512) ? (fs - 512) : min(c, fs);
    }
    __shared__ int red[NN];
    red[j] = g_RowTotI[j];
    __syncthreads();
    for (int off = 128; off > 0; off >>= 1) {
        if (j < off) red[j] += red[j + off];
        __syncthreads();
    }
    if (j == 0) g_TotalI = red[0];
}

// KC: expand — one warp per output step. Replay chunk-local prefix in
// registers, then 8 parallel Li lookups + REDUX. 8 warps/CTA, 250 CTAs.
__global__ void kC_expand(const float* __restrict__ h,
                          const float* __restrict__ offset,
                          const float* __restrict__ scale,
                          float* __restrict__ out) {
    __shared__ int   sm[40];
    __shared__ float shh[40];
    int blockBase = blockIdx.x * 8;              // first step of this CTA
    int cs = (blockBase / CHUNK) * CHUNK;        // chunk start of first warp
    int need = blockBase + 8 - cs;               // <= 32
    int tid = threadIdx.x;
    if (tid < need) { sm[tid] = g_meta[cs + tid]; shh[tid] = h[cs + tid]; }
    __syncthreads();

    int warpId = tid >> 5;
    int lane   = tid & 31;
    int t  = blockBase + warpId;                 // this warp's output step
    int ci = t / CHUNK;
    int t0 = ci * CHUNK;
    int lu0 = t0 - cs;                           // smem offset of chunk start
    int nsteps = t - t0 + 1;                     // steps to replay (1..25)

    int   c[8], oj[8];
    float xq[8];
    #pragma unroll
    for (int q = 0; q < 8; q++) {
        int j = lane + 32 * q;
        oj[q] = j * (j + 3) / 2;
        xq[q] = xval(j);
        c[q]  = g_centry[ci * NN + j];
    }

    for (int u = 0; u < nsteps; u++) {
        int   mt = sm[lu0 + u];
        float hc = shh[lu0 + u];
        if (mt == -1) {
            #pragma unroll
            for (int q = 0; q < 8; q++) {
                int j = lane + 32 * q;
                if (xq[q] < hc) c[q] = j + 1;
            }
        } else if (mt >= 0) {
            #pragma unroll
            for (int q = 0; q < 8; q++) c[q] = min(c[q], mt);
        }
    }

    // 8 independent lookups, issued together (MLP=8)
    int rv[8];
    #pragma unroll
    for (int q = 0; q < 8; q++) rv[q] = g_Li[oj[q] + c[q]];

    int s8 = ((rv[0] + rv[1]) + (rv[2] + rv[3])) +
             ((rv[4] + rv[5]) + (rv[6] + rv[7]));
    int tot = __reduce_add_sync(0xffffffffu, s8);

    if (lane == 0) {
        float numer = (float)(2 * tot - g_TotalI) * (1.0f / QSCALE);
        out[t] = numer * (1.0f / 32896.0f) * scale[0] + offset[0];
    }
}

extern "C" void kernel_launch(void* const* d_in, const int* in_sizes, int n_in,
                              void* d_out, int out_size) {
    const float* h      = (const float*)d_in[0];
    const float* raw    = (const float*)d_in[1];
    const float* offset = (const float*)d_in[2];
    const float* scale  = (const float*)d_in[3];
    float* out = (float*)d_out;

    kA_fused<<<96, 512>>>(raw, h);
    kB_scan<<<1, 256>>>();
    kC_expand<<<TT / 8, 256>>>(h, offset, scale, out);
}